// round 16
// baseline (speedup 1.0000x reference)
#include <cuda_runtime.h>
#include <cuda_bf16.h>
#include <math.h>
#include <stdint.h>

// ---------------------------------------------------------------- constants
#define ADIM 8
#define BDIM 16
#define HDIM 64
#define WDIM 64
#define SPATIAL (ADIM*BDIM*HDIM*WDIM)   // 524288
#define COUT 32
#define EPSV 1e-5f
#define NEG_SLOPE 0.2f

#define NPLANE 128            // ab = a*16+b
#define GW 66                 // padded slot grid width (h,w = -1..64)
#define SLOTS (GW*GW)         // 4356
#define MARG 72               // zero slots before payload
#define PSTRIDE 4752          // slots per (ab) plane (72 + 4608 + 67 <= 4752)
#define TGROUPS 18            // 18 * 256 = 4608 >= 4356
#define SLAB 392              // A slab rows per (block, dadb)

// ------------------------------------------------------------- scratch
__device__ float g_buf1[COUT * SPATIAL];
__device__ float g_buf2[COUT * SPATIAL];
__device__ float2 g_stats1[COUT];
__device__ float2 g_stats2[COUT];
__device__ __nv_bfloat16 g_X1[(size_t)NPLANE * PSTRIDE * 40];  // rows of 40 bf16
__device__ __nv_bfloat16 g_X2[(size_t)NPLANE * PSTRIDE * 72];  // rows of 72 bf16
// B fragments: [dadb(9)][tap(9)][chunk(NBC)][ntile(4)][lane(32)] x uint2
__device__ uint2 g_Bf1[9 * 9 * 2 * 4 * 32];
__device__ uint2 g_Bf2[9 * 9 * 4 * 4 * 32];

// product tables: (A kchunk, B chunk) pairs
__constant__ int PA16[3] = {0, 1, 0};
__constant__ int PB16[3] = {0, 0, 1};
__constant__ int PA32[6] = {0, 1, 2, 3, 0, 1};
__constant__ int PB32[6] = {0, 1, 0, 1, 2, 3};
__constant__ int ROWOFF[9] = {-GW-1, -GW, -GW+1, -1, 0, 1, GW-1, GW, GW+1};

// ------------------------------------------------------------- helpers
#define CP16(sa, g) \
    asm volatile("cp.async.cg.shared.global [%0], [%1], 16;" :: "r"(sa), "l"(g))
#define CP_COMMIT() asm volatile("cp.async.commit_group;")
#define CP_WAIT0()  asm volatile("cp.async.wait_group 0;" ::: "memory")

__device__ __forceinline__ uint32_t s2u(const void* p) {
    return (uint32_t)__cvta_generic_to_shared(p);
}
__device__ __forceinline__ unsigned short bfbits(__nv_bfloat16 v) {
    return *reinterpret_cast<unsigned short*>(&v);
}

#define LDMATX4(r, addr) \
    asm volatile("ldmatrix.sync.aligned.m8n8.x4.shared.b16 {%0,%1,%2,%3}, [%4];" \
        : "=r"((r)[0]), "=r"((r)[1]), "=r"((r)[2]), "=r"((r)[3]) : "r"(addr))

#define MMA16816(d, aq, b0, b1) \
    asm volatile("mma.sync.aligned.m16n8k16.row.col.f32.bf16.bf16.f32 " \
        "{%0,%1,%2,%3}, {%4,%5,%6,%7}, {%8,%9}, {%0,%1,%2,%3};" \
        : "+f"((d)[0]), "+f"((d)[1]), "+f"((d)[2]), "+f"((d)[3]) \
        : "r"((aq)[0]), "r"((aq)[1]), "r"((aq)[2]), "r"((aq)[3]), \
          "r"(b0), "r"(b1))

// ------------------------------------------------------------- weight prep
template<int CIN, int NBC>
__global__ void prep_w(const float* __restrict__ w, uint2* __restrict__ Bf)
{
    const int t = blockIdx.x * 256 + threadIdx.x;
    if (t >= 9 * 9 * NBC * 4 * 32) return;
    const int lane = t & 31;
    const int nt   = (t >> 5) & 3;
    int u = t >> 7;
    const int chunk = u % NBC;  u /= NBC;
    const int tap   = u % 9;
    const int dadb  = u / 9;

    const int n  = lane >> 2;
    const int k0 = (lane & 3) * 2;
    const int co = nt * 8 + n;
    const bool wantlo = (chunk >= NBC / 2);
    const int cibase  = (chunk % (NBC / 2)) * 16;

    unsigned short v[4];
    #pragma unroll
    for (int j = 0; j < 4; ++j) {
        const int k  = ((j >> 1) * 8) + k0 + (j & 1);   // k0,k0+1,k0+8,k0+9
        const int ci = cibase + k;
        const float wv = w[((size_t)co * CIN + ci) * 81 + dadb * 9 + tap];
        const __nv_bfloat16 hi = __float2bfloat16(wv);
        const __nv_bfloat16 lo = __float2bfloat16(wv - __bfloat162float(hi));
        v[j] = bfbits(wantlo ? lo : hi);
    }
    uint2 r;
    r.x = ((uint32_t)v[1] << 16) | v[0];
    r.y = ((uint32_t)v[3] << 16) | v[2];
    Bf[t] = r;
}

// ------------------------------------------------------------- X prep
__global__ void prep_x1(const float* __restrict__ img, __nv_bfloat16* __restrict__ X)
{
    const long gid = (long)blockIdx.x * 256 + threadIdx.x;
    if (gid >= (long)NPLANE * PSTRIDE * 5) return;
    const int c  = (int)(gid % 5);
    const int s  = (int)((gid / 5) % PSTRIDE);
    const int ab = (int)(gid / (5L * PSTRIDE));

    unsigned short row[8] = {0,0,0,0,0,0,0,0};
    const int slot = s - MARG;
    if (slot >= 0 && slot < SLOTS && c < 4) {
        const int ph = slot / GW, pw = slot % GW;
        if (ph >= 1 && ph <= 64 && pw >= 1 && pw <= 64) {
            const int base = ab * 4096 + (ph - 1) * 64 + (pw - 1);
            const bool wantlo = (c >= 2);
            const int ci0 = (c % 2) * 8;
            #pragma unroll
            for (int j = 0; j < 8; ++j) {
                const float v = img[(size_t)(ci0 + j) * SPATIAL + base];
                const __nv_bfloat16 hi = __float2bfloat16(v);
                row[j] = bfbits(wantlo
                    ? __float2bfloat16(v - __bfloat162float(hi)) : hi);
            }
        }
    }
    *reinterpret_cast<uint4*>(X + ((size_t)ab * PSTRIDE + s) * 40 + c * 8) =
        *reinterpret_cast<const uint4*>(row);
}

__global__ void prep_x2(const float* __restrict__ in, const float2* __restrict__ st,
                        __nv_bfloat16* __restrict__ X)
{
    const long gid = (long)blockIdx.x * 256 + threadIdx.x;
    if (gid >= (long)NPLANE * PSTRIDE * 9) return;
    const int c  = (int)(gid % 9);
    const int s  = (int)((gid / 9) % PSTRIDE);
    const int ab = (int)(gid / (9L * PSTRIDE));

    unsigned short row[8] = {0,0,0,0,0,0,0,0};
    const int slot = s - MARG;
    if (slot >= 0 && slot < SLOTS && c < 8) {
        const int ph = slot / GW, pw = slot % GW;
        if (ph >= 1 && ph <= 64 && pw >= 1 && pw <= 64) {
            const int base = ab * 4096 + (ph - 1) * 64 + (pw - 1);
            const bool wantlo = (c >= 4);
            const int ci0 = (c % 4) * 8;
            #pragma unroll
            for (int j = 0; j < 8; ++j) {
                const int ci = ci0 + j;
                const float2 s2 = st[ci];
                float v = in[(size_t)ci * SPATIAL + base];
                v = (v - s2.x) * s2.y;
                v = (v >= 0.f) ? v : NEG_SLOPE * v;
                const __nv_bfloat16 hi = __float2bfloat16(v);
                row[j] = bfbits(wantlo
                    ? __float2bfloat16(v - __bfloat162float(hi)) : hi);
            }
        }
    }
    *reinterpret_cast<uint4*>(X + ((size_t)ab * PSTRIDE + s) * 72 + c * 8) =
        *reinterpret_cast<const uint4*>(row);
}

// ------------------------------------------------------------- MMA conv
// Block: 256 thr = 8 warps; M = 256 slots, N = 32; acc over (da,db) x 9 taps.
// Ping-pong double-buffered A+B segment loads: load(i+1) overlaps compute(i).
template<int CIN>
__global__ __launch_bounds__(256, 2)
void conv_mma(const __nv_bfloat16* __restrict__ X,
              const uint2* __restrict__ Bf,
              float* __restrict__ y)
{
    constexpr int ROWE  = (CIN == 16) ? 40 : 72;     // bf16 per A row
    constexpr int ROWB  = ROWE * 2;                  // bytes (80 | 144)
    constexpr int NKA   = CIN / 8;                   // A kchunks (2 | 4)
    constexpr int NBC   = CIN / 8;                   // B chunks  (2 | 4)
    constexpr int NPROD = (CIN == 16) ? 3 : 6;
    constexpr int ABYTES = SLAB * ROWB;
    constexpr int BBYTES = 9 * NBC * 4 * 256;
    constexpr int BUFB   = ABYTES + BBYTES;          // one segment buffer

    extern __shared__ char smem[];
    const uint32_t sb = s2u(smem);

    const int ab = blockIdx.x, a = ab >> 4, b = ab & 15;
    const int tg = blockIdx.y;
    const int tid = threadIdx.x, warp = tid >> 5, lane = tid & 31;
    const int sidx0 = tg * 256 + 5;          // slab global row start (s index)

    // valid (da,db) segment list (block-uniform)
    int plist[9]; int nv = 0;
    for (int da = 0; da < 3; ++da) {
        const int ia = a + da - 1;
        if ((unsigned)ia >= (unsigned)ADIM) continue;
        for (int db = 0; db < 3; ++db) {
            const int ib = b + db - 1;
            if ((unsigned)ib >= (unsigned)BDIM) continue;
            plist[nv++] = (ia * 16 + ib) | ((da * 3 + db) << 8);
        }
    }

    auto load_seg = [&](int idx, uint32_t dst) {
        const int code = plist[idx];
        const int iab  = code & 255;
        const int dadb = code >> 8;
        const char* ag = (const char*)(X + ((size_t)iab * PSTRIDE + sidx0) * ROWE);
        for (int e = tid; e < ABYTES / 16; e += 256)
            CP16(dst + e * 16, ag + (size_t)e * 16);
        const char* bg = (const char*)(Bf + (size_t)dadb * 9 * NBC * 4 * 32);
        for (int e = tid; e < BBYTES / 16; e += 256)
            CP16(dst + ABYTES + e * 16, bg + (size_t)e * 16);
        CP_COMMIT();
    };

    float acc[2][4][4] = {};                 // [mtile][ntile][frag]

    load_seg(0, sb);                         // prologue
    for (int i = 0; i < nv; ++i) {
        const uint32_t Abase = sb + (i & 1) * BUFB;
        const uint32_t Bbase = Abase + ABYTES;

        CP_WAIT0();        // segment i landed (only group outstanding)
        __syncthreads();   // visible to all; compute(i-1) finished block-wide

        if (i + 1 < nv)    // prefetch next segment into the other buffer
            load_seg(i + 1, sb + ((i + 1) & 1) * BUFB);

        #pragma unroll 1
        for (int tap = 0; tap < 9; ++tap) {
            // B fragments for this tap (per-lane layout, conflict-free)
            uint32_t bq[NBC][4][2];
            #pragma unroll
            for (int ch = 0; ch < NBC; ++ch)
                #pragma unroll
                for (int nt = 0; nt < 4; ++nt) {
                    const uint32_t addr = Bbase +
                        ((((tap * NBC + ch) * 4 + nt) * 32 + lane) << 3);
                    asm volatile("ld.shared.v2.b32 {%0,%1}, [%2];"
                        : "=r"(bq[ch][nt][0]), "=r"(bq[ch][nt][1]) : "r"(addr));
                }

            const int rowoff = ROWOFF[tap];
            #pragma unroll
            for (int mt = 0; mt < 2; ++mt) {
                const int baserow = 67 + rowoff + warp * 32 + mt * 16 + (lane & 15);
                uint32_t aq[NKA][4];
                #pragma unroll
                for (int kc = 0; kc < NKA; ++kc) {
                    const uint32_t addr = Abase + baserow * ROWB +
                                          kc * 32 + ((lane >> 4) << 4);
                    LDMATX4(aq[kc], addr);
                }
                #pragma unroll
                for (int nt = 0; nt < 4; ++nt)
                    #pragma unroll
                    for (int p = 0; p < NPROD; ++p) {
                        const int ka = (CIN == 16) ? PA16[p] : PA32[p];
                        const int kb = (CIN == 16) ? PB16[p] : PB32[p];
                        MMA16816(acc[mt][nt], aq[ka],
                                 bq[kb][nt][0], bq[kb][nt][1]);
                    }
            }
        }
    }

    // Epilogue: scatter valid interior slots to y[co][spatial]
    const int slotb = tg * 256 + warp * 32;
    #pragma unroll
    for (int mt = 0; mt < 2; ++mt)
        #pragma unroll
        for (int half = 0; half < 2; ++half) {
            const int slot = slotb + mt * 16 + (lane >> 2) + half * 8;
            if (slot < SLOTS) {
                const int ph = slot / GW, pw = slot % GW;
                if (ph >= 1 && ph <= 64 && pw >= 1 && pw <= 64) {
                    float* yb = y + ab * 4096 + (ph - 1) * 64 + (pw - 1);
                    #pragma unroll
                    for (int nt = 0; nt < 4; ++nt)
                        #pragma unroll
                        for (int cp = 0; cp < 2; ++cp) {
                            const int co = nt * 8 + (lane & 3) * 2 + cp;
                            yb[(size_t)co * SPATIAL] = acc[mt][nt][half * 2 + cp];
                        }
                }
            }
        }
}

// ------------------------------------------------------------- stats / norm
__global__ __launch_bounds__(1024)
void stats_kernel(const float* __restrict__ buf, float2* __restrict__ stats)
{
    const int co = blockIdx.x;
    const float4* p = reinterpret_cast<const float4*>(buf + (size_t)co * SPATIAL);
    const int nvec = SPATIAL / 4;

    float s = 0.f, s2 = 0.f;
    for (int i = threadIdx.x; i < nvec; i += 1024) {
        float4 v = p[i];
        s  += v.x + v.y + v.z + v.w;
        s2 += v.x * v.x + v.y * v.y + v.z * v.z + v.w * v.w;
    }
    #pragma unroll
    for (int o = 16; o > 0; o >>= 1) {
        s  += __shfl_down_sync(0xffffffffu, s,  o);
        s2 += __shfl_down_sync(0xffffffffu, s2, o);
    }
    __shared__ float rs[32], rs2[32];
    const int lane = threadIdx.x & 31, wid = threadIdx.x >> 5;
    if (lane == 0) { rs[wid] = s; rs2[wid] = s2; }
    __syncthreads();
    if (wid == 0) {
        s  = rs[lane];
        s2 = rs2[lane];
        #pragma unroll
        for (int o = 16; o > 0; o >>= 1) {
            s  += __shfl_down_sync(0xffffffffu, s,  o);
            s2 += __shfl_down_sync(0xffffffffu, s2, o);
        }
        if (lane == 0) {
            const float inv_n = 1.0f / (float)SPATIAL;
            const float mean  = s * inv_n;
            const float var   = fmaxf(s2 * inv_n - mean * mean, 0.f);
            stats[co] = make_float2(mean, rsqrtf(var + EPSV));
        }
    }
}

__global__ __launch_bounds__(256)
void normleaky_kernel(const float* __restrict__ in,
                      const float2* __restrict__ stats,
                      float* __restrict__ out)
{
    const int nvec = COUT * SPATIAL / 4;
    const float4* ip = reinterpret_cast<const float4*>(in);
    float4* op = reinterpret_cast<float4*>(out);
    for (int i = blockIdx.x * blockDim.x + threadIdx.x; i < nvec;
         i += gridDim.x * blockDim.x) {
        const int co = (i * 4) >> 19;
        const float2 st = stats[co];
        float4 v = ip[i];
        float a0 = (v.x - st.x) * st.y;
        float a1 = (v.y - st.x) * st.y;
        float a2 = (v.z - st.x) * st.y;
        float a3 = (v.w - st.x) * st.y;
        v.x = a0 >= 0.f ? a0 : NEG_SLOPE * a0;
        v.y = a1 >= 0.f ? a1 : NEG_SLOPE * a1;
        v.z = a2 >= 0.f ? a2 : NEG_SLOPE * a2;
        v.w = a3 >= 0.f ? a3 : NEG_SLOPE * a3;
        op[i] = v;
    }
}

// ------------------------------------------------------------- launch
extern "C" void kernel_launch(void* const* d_in, const int* in_sizes, int n_in,
                              void* d_out, int out_size)
{
    (void)in_sizes; (void)n_in; (void)out_size;
    const float* image = (const float*)d_in[0];
    const float* w1    = (const float*)d_in[1];
    const float* w2    = (const float*)d_in[2];
    float* out = (float*)d_out;

    float*  buf1; cudaGetSymbolAddress((void**)&buf1, g_buf1);
    float*  buf2; cudaGetSymbolAddress((void**)&buf2, g_buf2);
    float2* st1;  cudaGetSymbolAddress((void**)&st1,  g_stats1);
    float2* st2;  cudaGetSymbolAddress((void**)&st2,  g_stats2);
    __nv_bfloat16* x1; cudaGetSymbolAddress((void**)&x1, g_X1);
    __nv_bfloat16* x2; cudaGetSymbolAddress((void**)&x2, g_X2);
    uint2* bf1; cudaGetSymbolAddress((void**)&bf1, g_Bf1);
    uint2* bf2; cudaGetSymbolAddress((void**)&bf2, g_Bf2);

    const int smem1 = 2 * (SLAB * 80  + 9 * 2 * 4 * 256);   // 99584
    const int smem2 = 2 * (SLAB * 144 + 9 * 4 * 4 * 256);   // 186624
    cudaFuncSetAttribute(conv_mma<16>,
                         cudaFuncAttributeMaxDynamicSharedMemorySize, smem1);
    cudaFuncSetAttribute(conv_mma<32>,
                         cudaFuncAttributeMaxDynamicSharedMemorySize, smem2);

    const dim3 mgrid(NPLANE, TGROUPS);
    const int px1 = (int)(((long)NPLANE * PSTRIDE * 5 + 255) / 256);
    const int px2 = (int)(((long)NPLANE * PSTRIDE * 9 + 255) / 256);

    prep_w<16, 2><<<81, 256>>>(w1, bf1);
    prep_w<32, 4><<<162, 256>>>(w2, bf2);
    prep_x1<<<px1, 256>>>(image, x1);

    conv_mma<16><<<mgrid, 256, smem1>>>(x1, bf1, buf1);
    stats_kernel<<<COUT, 1024>>>(buf1, st1);
    prep_x2<<<px2, 256>>>(buf1, st1, x2);

    conv_mma<32><<<mgrid, 256, smem2>>>(x2, bf2, buf2);
    stats_kernel<<<COUT, 1024>>>(buf2, st2);
    normleaky_kernel<<<2048, 256>>>(buf2, st2, out);
}

// round 17
// speedup vs baseline: 3.4444x; 3.4444x over previous
#include <cuda_runtime.h>
#include <cuda_fp16.h>
#include <math.h>
#include <stdint.h>

// ---------------------------------------------------------------- constants
#define ADIM 8
#define BDIM 16
#define HDIM 64
#define WDIM 64
#define SPATIAL (ADIM*BDIM*HDIM*WDIM)   // 524288
#define COUT 32
#define EPSV 1e-5f
#define NEG_SLOPE 0.2f

#define NPLANE 128            // ab = a*16+b
#define GW 66                 // padded slot grid width (h,w = -1..64)
#define SLOTS (GW*GW)         // 4356
#define MARG 72               // zero slots before payload
#define PSTRIDE 4752          // slots per (ab) plane
#define TGROUPS 18            // 18 * 256 = 4608 >= 4356
#define SLAB 392              // A slab rows per (block, dadb)

// ------------------------------------------------------------- scratch
__device__ float g_buf1[COUT * SPATIAL];
__device__ float g_buf2[COUT * SPATIAL];
__device__ float2 g_stats1[COUT];
__device__ float2 g_stats2[COUT];
__device__ __half g_X1[(size_t)NPLANE * PSTRIDE * 40];  // rows: hi(16)|lo(16)|pad8
__device__ __half g_X2[(size_t)NPLANE * PSTRIDE * 72];  // rows: hi(32)|lo(32)|pad8
// B fragments: [dadb(9)][tap(9)][chunk(NBC)][ntile(4)][lane(32)] x uint2
__device__ uint2 g_Bf1[9 * 9 * 1 * 4 * 32];   // fp16 weights, 1 chunk (K16)
__device__ uint2 g_Bf2[9 * 9 * 2 * 4 * 32];   // 2 chunks (K32)

__constant__ int ROWOFF[9] = {-GW-1, -GW, -GW+1, -1, 0, 1, GW-1, GW, GW+1};

// ------------------------------------------------------------- helpers
#define CP16(sa, g) \
    asm volatile("cp.async.cg.shared.global [%0], [%1], 16;" :: "r"(sa), "l"(g))
#define CP_COMMIT() asm volatile("cp.async.commit_group;")
#define CP_WAIT0()  asm volatile("cp.async.wait_group 0;" ::: "memory")

__device__ __forceinline__ uint32_t s2u(const void* p) {
    return (uint32_t)__cvta_generic_to_shared(p);
}
__device__ __forceinline__ unsigned short hbits(__half v) {
    return *reinterpret_cast<unsigned short*>(&v);
}

#define LDMATX4(r, addr) \
    asm volatile("ldmatrix.sync.aligned.m8n8.x4.shared.b16 {%0,%1,%2,%3}, [%4];" \
        : "=r"((r)[0]), "=r"((r)[1]), "=r"((r)[2]), "=r"((r)[3]) : "r"(addr))

#define MMA16816(d, aq, b0, b1) \
    asm volatile("mma.sync.aligned.m16n8k16.row.col.f32.f16.f16.f32 " \
        "{%0,%1,%2,%3}, {%4,%5,%6,%7}, {%8,%9}, {%0,%1,%2,%3};" \
        : "+f"((d)[0]), "+f"((d)[1]), "+f"((d)[2]), "+f"((d)[3]) \
        : "r"((aq)[0]), "r"((aq)[1]), "r"((aq)[2]), "r"((aq)[3]), \
          "r"(b0), "r"(b1))

// ------------------------------------------------------------- weight prep
// frag layout per (dadb, tap, chunk, ntile, lane): b0={B[k0][n],B[k0+1][n]},
// b1={B[k0+8][n],B[k0+9][n]}, k0=(lane&3)*2, n=lane>>2, co=ntile*8+n,
// ci = chunk*16 + k.  Single fp16 weight value (no hi/lo split on W).
template<int CIN, int NBC>
__global__ void prep_w(const float* __restrict__ w, uint2* __restrict__ Bf)
{
    const int t = blockIdx.x * 256 + threadIdx.x;
    if (t >= 9 * 9 * NBC * 4 * 32) return;
    const int lane = t & 31;
    const int nt   = (t >> 5) & 3;
    int u = t >> 7;
    const int chunk = u % NBC;  u /= NBC;
    const int tap   = u % 9;
    const int dadb  = u / 9;

    const int n  = lane >> 2;
    const int k0 = (lane & 3) * 2;
    const int co = nt * 8 + n;

    unsigned short v[4];
    #pragma unroll
    for (int j = 0; j < 4; ++j) {
        const int k  = ((j >> 1) * 8) + k0 + (j & 1);   // k0,k0+1,k0+8,k0+9
        const int ci = chunk * 16 + k;
        const float wv = w[((size_t)co * CIN + ci) * 81 + dadb * 9 + tap];
        v[j] = hbits(__float2half(wv));
    }
    uint2 r;
    r.x = ((uint32_t)v[1] << 16) | v[0];
    r.y = ((uint32_t)v[3] << 16) | v[2];
    Bf[t] = r;
}

// ------------------------------------------------------------- X prep
// fp16 hi/lo split of x (x = hi + lo, lo error ~2^-22).
__global__ void prep_x1(const float* __restrict__ img, __half* __restrict__ X)
{
    const long gid = (long)blockIdx.x * 256 + threadIdx.x;
    if (gid >= (long)NPLANE * PSTRIDE * 5) return;
    const int c  = (int)(gid % 5);
    const int s  = (int)((gid / 5) % PSTRIDE);
    const int ab = (int)(gid / (5L * PSTRIDE));

    unsigned short row[8] = {0,0,0,0,0,0,0,0};
    const int slot = s - MARG;
    if (slot >= 0 && slot < SLOTS && c < 4) {
        const int ph = slot / GW, pw = slot % GW;
        if (ph >= 1 && ph <= 64 && pw >= 1 && pw <= 64) {
            const int base = ab * 4096 + (ph - 1) * 64 + (pw - 1);
            const bool wantlo = (c >= 2);
            const int ci0 = (c % 2) * 8;
            #pragma unroll
            for (int j = 0; j < 8; ++j) {
                const float v = img[(size_t)(ci0 + j) * SPATIAL + base];
                const __half hi = __float2half(v);
                row[j] = hbits(wantlo ? __float2half(v - __half2float(hi)) : hi);
            }
        }
    }
    *reinterpret_cast<uint4*>(X + ((size_t)ab * PSTRIDE + s) * 40 + c * 8) =
        *reinterpret_cast<const uint4*>(row);
}

__global__ void prep_x2(const float* __restrict__ in, const float2* __restrict__ st,
                        __half* __restrict__ X)
{
    const long gid = (long)blockIdx.x * 256 + threadIdx.x;
    if (gid >= (long)NPLANE * PSTRIDE * 9) return;
    const int c  = (int)(gid % 9);
    const int s  = (int)((gid / 9) % PSTRIDE);
    const int ab = (int)(gid / (9L * PSTRIDE));

    unsigned short row[8] = {0,0,0,0,0,0,0,0};
    const int slot = s - MARG;
    if (slot >= 0 && slot < SLOTS && c < 8) {
        const int ph = slot / GW, pw = slot % GW;
        if (ph >= 1 && ph <= 64 && pw >= 1 && pw <= 64) {
            const int base = ab * 4096 + (ph - 1) * 64 + (pw - 1);
            const bool wantlo = (c >= 4);
            const int ci0 = (c % 4) * 8;
            #pragma unroll
            for (int j = 0; j < 8; ++j) {
                const int ci = ci0 + j;
                const float2 s2 = st[ci];
                float v = in[(size_t)ci * SPATIAL + base];
                v = (v - s2.x) * s2.y;
                v = (v >= 0.f) ? v : NEG_SLOPE * v;
                const __half hi = __float2half(v);
                row[j] = hbits(wantlo ? __float2half(v - __half2float(hi)) : hi);
            }
        }
    }
    *reinterpret_cast<uint4*>(X + ((size_t)ab * PSTRIDE + s) * 72 + c * 8) =
        *reinterpret_cast<const uint4*>(row);
}

// ------------------------------------------------------------- MMA conv
// Block: 256 thr = 8 warps; M = 256 slots, N = 32; acc over (da,db) x 9 taps.
// fp16 2-product (conv1) / 4-product (conv2): ka = p, kb = p&1 (0 for conv1).
template<int CIN>
__global__ __launch_bounds__(256, 2)
void conv_mma(const __half* __restrict__ X,
              const uint2* __restrict__ Bf,
              float* __restrict__ y)
{
    constexpr int ROWE  = (CIN == 16) ? 40 : 72;     // halfs per A row
    constexpr int ROWB  = ROWE * 2;                  // bytes (80 | 144)
    constexpr int NKA   = CIN / 8;                   // A kchunks (2 | 4)
    constexpr int NBC   = CIN / 16;                  // B chunks  (1 | 2)
    constexpr int NPROD = NKA;                       // 2 | 4 products
    constexpr int ABYTES = SLAB * ROWB;
    constexpr int BBYTES = 9 * NBC * 4 * 256;
    constexpr int BUFB   = ABYTES + BBYTES;          // one segment buffer

    extern __shared__ char smem[];
    const uint32_t sb = s2u(smem);

    const int ab = blockIdx.x, a = ab >> 4, b = ab & 15;
    const int tg = blockIdx.y;
    const int tid = threadIdx.x, warp = tid >> 5, lane = tid & 31;
    const int sidx0 = tg * 256 + 5;          // slab global row start (s index)

    // valid (da,db) segment list (block-uniform)
    int plist[9]; int nv = 0;
    for (int da = 0; da < 3; ++da) {
        const int ia = a + da - 1;
        if ((unsigned)ia >= (unsigned)ADIM) continue;
        for (int db = 0; db < 3; ++db) {
            const int ib = b + db - 1;
            if ((unsigned)ib >= (unsigned)BDIM) continue;
            plist[nv++] = (ia * 16 + ib) | ((da * 3 + db) << 8);
        }
    }

    auto load_seg = [&](int idx, uint32_t dst) {
        const int code = plist[idx];
        const int iab  = code & 255;
        const int dadb = code >> 8;
        const char* ag = (const char*)(X + ((size_t)iab * PSTRIDE + sidx0) * ROWE);
        for (int e = tid; e < ABYTES / 16; e += 256)
            CP16(dst + e * 16, ag + (size_t)e * 16);
        const char* bg = (const char*)(Bf + (size_t)dadb * 9 * NBC * 4 * 32);
        for (int e = tid; e < BBYTES / 16; e += 256)
            CP16(dst + ABYTES + e * 16, bg + (size_t)e * 16);
        CP_COMMIT();
    };

    float acc[2][4][4] = {};                 // [mtile][ntile][frag]

    load_seg(0, sb);                         // prologue
    for (int i = 0; i < nv; ++i) {
        const uint32_t Abase = sb + (i & 1) * BUFB;
        const uint32_t Bbase = Abase + ABYTES;

        CP_WAIT0();        // segment i landed (only group outstanding)
        __syncthreads();   // visible to all; compute(i-1) finished block-wide

        if (i + 1 < nv)    // prefetch next segment into the other buffer
            load_seg(i + 1, sb + ((i + 1) & 1) * BUFB);

        #pragma unroll 1
        for (int tap = 0; tap < 9; ++tap) {
            // B fragments for this tap (per-lane layout, conflict-free)
            uint32_t bq[NBC][4][2];
            #pragma unroll
            for (int ch = 0; ch < NBC; ++ch)
                #pragma unroll
                for (int nt = 0; nt < 4; ++nt) {
                    const uint32_t addr = Bbase +
                        ((((tap * NBC + ch) * 4 + nt) * 32 + lane) << 3);
                    asm volatile("ld.shared.v2.b32 {%0,%1}, [%2];"
                        : "=r"(bq[ch][nt][0]), "=r"(bq[ch][nt][1]) : "r"(addr));
                }

            const int rowoff = ROWOFF[tap];
            #pragma unroll
            for (int mt = 0; mt < 2; ++mt) {
                const int baserow = 67 + rowoff + warp * 32 + mt * 16 + (lane & 15);
                uint32_t aq[NKA][4];
                #pragma unroll
                for (int kc = 0; kc < NKA; ++kc) {
                    const uint32_t addr = Abase + baserow * ROWB +
                                          kc * 32 + ((lane >> 4) << 4);
                    LDMATX4(aq[kc], addr);
                }
                #pragma unroll
                for (int nt = 0; nt < 4; ++nt)
                    #pragma unroll
                    for (int p = 0; p < NPROD; ++p) {
                        const int kb = (CIN == 16) ? 0 : (p & 1);
                        MMA16816(acc[mt][nt], aq[p],
                                 bq[kb][nt][0], bq[kb][nt][1]);
                    }
            }
        }
    }

    // Epilogue: scatter valid interior slots to y[co][spatial]
    const int slotb = tg * 256 + warp * 32;
    #pragma unroll
    for (int mt = 0; mt < 2; ++mt)
        #pragma unroll
        for (int half = 0; half < 2; ++half) {
            const int slot = slotb + mt * 16 + (lane >> 2) + half * 8;
            if (slot < SLOTS) {
                const int ph = slot / GW, pw = slot % GW;
                if (ph >= 1 && ph <= 64 && pw >= 1 && pw <= 64) {
                    float* yb = y + ab * 4096 + (ph - 1) * 64 + (pw - 1);
                    #pragma unroll
                    for (int nt = 0; nt < 4; ++nt)
                        #pragma unroll
                        for (int cp = 0; cp < 2; ++cp) {
                            const int co = nt * 8 + (lane & 3) * 2 + cp;
                            yb[(size_t)co * SPATIAL] = acc[mt][nt][half * 2 + cp];
                        }
                }
            }
        }
}

// ------------------------------------------------------------- stats / norm
__global__ __launch_bounds__(1024)
void stats_kernel(const float* __restrict__ buf, float2* __restrict__ stats)
{
    const int co = blockIdx.x;
    const float4* p = reinterpret_cast<const float4*>(buf + (size_t)co * SPATIAL);
    const int nvec = SPATIAL / 4;

    float s = 0.f, s2 = 0.f;
    for (int i = threadIdx.x; i < nvec; i += 1024) {
        float4 v = p[i];
        s  += v.x + v.y + v.z + v.w;
        s2 += v.x * v.x + v.y * v.y + v.z * v.z + v.w * v.w;
    }
    #pragma unroll
    for (int o = 16; o > 0; o >>= 1) {
        s  += __shfl_down_sync(0xffffffffu, s,  o);
        s2 += __shfl_down_sync(0xffffffffu, s2, o);
    }
    __shared__ float rs[32], rs2[32];
    const int lane = threadIdx.x & 31, wid = threadIdx.x >> 5;
    if (lane == 0) { rs[wid] = s; rs2[wid] = s2; }
    __syncthreads();
    if (wid == 0) {
        s  = rs[lane];
        s2 = rs2[lane];
        #pragma unroll
        for (int o = 16; o > 0; o >>= 1) {
            s  += __shfl_down_sync(0xffffffffu, s,  o);
            s2 += __shfl_down_sync(0xffffffffu, s2, o);
        }
        if (lane == 0) {
            const float inv_n = 1.0f / (float)SPATIAL;
            const float mean  = s * inv_n;
            const float var   = fmaxf(s2 * inv_n - mean * mean, 0.f);
            stats[co] = make_float2(mean, rsqrtf(var + EPSV));
        }
    }
}

__global__ __launch_bounds__(256)
void normleaky_kernel(const float* __restrict__ in,
                      const float2* __restrict__ stats,
                      float* __restrict__ out)
{
    const int nvec = COUT * SPATIAL / 4;
    const float4* ip = reinterpret_cast<const float4*>(in);
    float4* op = reinterpret_cast<float4*>(out);
    for (int i = blockIdx.x * blockDim.x + threadIdx.x; i < nvec;
         i += gridDim.x * blockDim.x) {
        const int co = (i * 4) >> 19;
        const float2 st = stats[co];
        float4 v = ip[i];
        float a0 = (v.x - st.x) * st.y;
        float a1 = (v.y - st.x) * st.y;
        float a2 = (v.z - st.x) * st.y;
        float a3 = (v.w - st.x) * st.y;
        v.x = a0 >= 0.f ? a0 : NEG_SLOPE * a0;
        v.y = a1 >= 0.f ? a1 : NEG_SLOPE * a1;
        v.z = a2 >= 0.f ? a2 : NEG_SLOPE * a2;
        v.w = a3 >= 0.f ? a3 : NEG_SLOPE * a3;
        op[i] = v;
    }
}

// ------------------------------------------------------------- launch
extern "C" void kernel_launch(void* const* d_in, const int* in_sizes, int n_in,
                              void* d_out, int out_size)
{
    (void)in_sizes; (void)n_in; (void)out_size;
    const float* image = (const float*)d_in[0];
    const float* w1    = (const float*)d_in[1];
    const float* w2    = (const float*)d_in[2];
    float* out = (float*)d_out;

    float*  buf1; cudaGetSymbolAddress((void**)&buf1, g_buf1);
    float*  buf2; cudaGetSymbolAddress((void**)&buf2, g_buf2);
    float2* st1;  cudaGetSymbolAddress((void**)&st1,  g_stats1);
    float2* st2;  cudaGetSymbolAddress((void**)&st2,  g_stats2);
    __half* x1; cudaGetSymbolAddress((void**)&x1, g_X1);
    __half* x2; cudaGetSymbolAddress((void**)&x2, g_X2);
    uint2* bf1; cudaGetSymbolAddress((void**)&bf1, g_Bf1);
    uint2* bf2; cudaGetSymbolAddress((void**)&bf2, g_Bf2);

    const int smem1 = 2 * (SLAB * 80  + 9 * 1 * 4 * 256);   // 2*40576 = 81152
    const int smem2 = 2 * (SLAB * 144 + 9 * 2 * 4 * 256);   // 2*74880 = 149760
    cudaFuncSetAttribute(conv_mma<16>,
                         cudaFuncAttributeMaxDynamicSharedMemorySize, smem1);
    cudaFuncSetAttribute(conv_mma<32>,
                         cudaFuncAttributeMaxDynamicSharedMemorySize, smem2);

    const dim3 mgrid(NPLANE, TGROUPS);
    const int px1 = (int)(((long)NPLANE * PSTRIDE * 5 + 255) / 256);
    const int px2 = (int)(((long)NPLANE * PSTRIDE * 9 + 255) / 256);

    prep_w<16, 1><<<41, 256>>>(w1, bf1);
    prep_w<32, 2><<<81, 256>>>(w2, bf2);
    prep_x1<<<px1, 256>>>(image, x1);

    conv_mma<16><<<mgrid, 256, smem1>>>(x1, bf1, buf1);
    stats_kernel<<<COUT, 1024>>>(buf1, st1);
    prep_x2<<<px2, 256>>>(buf1, st1, x2);

    conv_mma<32><<<mgrid, 256, smem2>>>(x2, bf2, buf2);
    stats_kernel<<<COUT, 1024>>>(buf2, st2);
    normleaky_kernel<<<2048, 256>>>(buf2, st2, out);
}